// round 15
// baseline (speedup 1.0000x reference)
#include <cuda_runtime.h>
#include <cuda_fp16.h>
#include <math.h>
#include <stdint.h>

// Problem shape (fixed)
#define D       256
#define NROWS   16384
#define KCODES  4096

// Pass-1 GEMM tiling: CTA 64x128, 8 warps (2m x 4n), warp tile 32x32
#define BM      64
#define BN      128
#define KC      64                 // fp16 elems per staged chunk (=128B rows)
#define NCHUNK  (D / KC)           // 4
#define KSPLIT  (KCODES / BN)      // 32
#define MARGIN  1.5f
#define HALF_ROWS (NROWS / 2)      // 8192

// smem: stage = A(64x128B=8K) + B(128x128B=16K) = 24K, double buffered
#define STAGE_BYTES   24576
#define A_OFF         0
#define B_OFF         8192
#define SMEM_CBN      (2 * STAGE_BYTES)
#define SMEM_TOTAL    (SMEM_CBN + 512)

#define SWZ(x) ((x) ^ (((x) >> 3) & 0x70))

// ---------------------------------------------------------------------------
__device__ __forceinline__ uint32_t smem_u32(const void* p) {
    uint32_t a;
    asm("{ .reg .u64 t; cvta.to.shared.u64 t, %1; cvt.u32.u64 %0, t; }" : "=r"(a) : "l"(p));
    return a;
}
#define CP_ASYNC16(dst, src) \
    asm volatile("cp.async.cg.shared.global [%0], [%1], 16;" :: "r"(dst), "l"(src))
#define CP_COMMIT() asm volatile("cp.async.commit_group;" ::: "memory")
#define CP_WAIT(n)  asm volatile("cp.async.wait_group %0;" :: "n"(n) : "memory")
#define LDSM4(r0, r1, r2, r3, addr) \
    asm volatile("ldmatrix.sync.aligned.m8n8.x4.shared.b16 {%0,%1,%2,%3}, [%4];" \
                 : "=r"(r0), "=r"(r1), "=r"(r2), "=r"(r3) : "r"(addr))
#define MMA_F16(c, a, b0, b1) \
    asm volatile("mma.sync.aligned.m16n8k16.row.col.f16.f16.f16.f16 " \
                 "{%0,%1}, {%2,%3,%4,%5}, {%6,%7}, {%0,%1};" \
                 : "+r"((c)[0]), "+r"((c)[1]) \
                 : "r"((a)[0]), "r"((a)[1]), "r"((a)[2]), "r"((a)[3]), "r"(b0), "r"(b1))

// ---------------------------------------------------------------------------
// Scratch
// ---------------------------------------------------------------------------
__device__ __half g_zeH[NROWS * D];
__device__ __half g_cbH[KCODES * D];
__device__ float g_cbnorm[KCODES];
__device__ int   g_counts[KCODES];
__device__ float g_loss;
__device__ unsigned int g_done;
__device__ float g_tval[KSPLIT * NROWS * 3];   // [split][row][3]
__device__ int   g_tidx[KSPLIT * NROWS * 3];

// ---------------------------------------------------------------------------
// Fused prep: blocks [0,4096) convert ze -> fp16; blocks [4096,4608) convert
// cb -> fp16 + fp32 norms + zero counters.
// ---------------------------------------------------------------------------
#define ZE_BLOCKS ((NROWS * D / 4) / 256)        // 4096
#define CB_BLOCKS (KCODES / 8)                   // 512

__global__ void prep_kernel(const float* __restrict__ ze,
                            const float* __restrict__ cb) {
    const int tid = threadIdx.x;
    if (blockIdx.x < ZE_BLOCKS) {
        int idx = blockIdx.x * 256 + tid;        // float4 index
        float4 v = ((const float4*)ze)[idx];
        __half2* o = (__half2*)g_zeH;
        o[idx * 2 + 0] = __floats2half2_rn(v.x, v.y);
        o[idx * 2 + 1] = __floats2half2_rn(v.z, v.w);
        return;
    }
    const int bb = blockIdx.x - ZE_BLOCKS;
    const int gid = bb * 256 + tid;
    if (gid < KCODES) g_counts[gid] = 0;
    if (gid == 0) { g_loss = 0.f; g_done = 0u; }

    const int warp = tid >> 5, lane = tid & 31;
    const int code = bb * 8 + warp;
    const float* row = cb + (size_t)code * D;
    float s = 0.f;
#pragma unroll
    for (int i = 0; i < D / 32; i++) {
        int j = lane + i * 32;
        float x = row[j];
        g_cbH[(size_t)code * D + j] = __float2half_rn(x);
        s = fmaf(x, x, s);
    }
#pragma unroll
    for (int o = 16; o; o >>= 1) s += __shfl_xor_sync(0xffffffffu, s, o);
    if (lane == 0) g_cbnorm[code] = s;
}

// ---------------------------------------------------------------------------
// top-3 insert (ascending)
// ---------------------------------------------------------------------------
__device__ __forceinline__ void ins3(float* tv, int* ti, float v, int id) {
    if (v < tv[0]) {
        tv[2] = tv[1]; ti[2] = ti[1];
        tv[1] = tv[0]; ti[1] = ti[0];
        tv[0] = v;     ti[0] = id;
    } else if (v < tv[1]) {
        tv[2] = tv[1]; ti[2] = ti[1];
        tv[1] = v;     ti[1] = id;
    } else if (v < tv[2]) {
        tv[2] = v;     ti[2] = id;
    }
}

// ---------------------------------------------------------------------------
// Pass 1: fp16 mma.sync (f16 accum) distance GEMM, fused top-3 per 128-code
// split. grid = (rows/BM, KSPLIT), 256 threads, 4 CTAs/SM. rowBase selects
// the row half.
// ---------------------------------------------------------------------------
extern __shared__ char dyn_smem[];

__device__ __forceinline__ void copy_chunk(uint32_t st, int ch, int row0,
                                           int kbase, int tid) {
    const __half* Az = g_zeH + (size_t)row0 * D + ch * KC;
    const __half* Bz = g_cbH + (size_t)kbase * D + ch * KC;
#pragma unroll
    for (int it = 0; it < 2; it++) {           // A: 64 rows x 8 granules
        int idx = tid + it * 256;
        int r = idx >> 3, g = idx & 7;
        CP_ASYNC16(st + A_OFF + SWZ((uint32_t)(r * 128 + g * 16)),
                   Az + (size_t)r * D + g * 8);
    }
#pragma unroll
    for (int it = 0; it < 4; it++) {           // B: 128 rows x 8 granules
        int idx = tid + it * 256;
        int r = idx >> 3, g = idx & 7;
        CP_ASYNC16(st + B_OFF + SWZ((uint32_t)(r * 128 + g * 16)),
                   Bz + (size_t)r * D + g * 8);
    }
}

__global__ void __launch_bounds__(256, 4) pass1_kernel(int rowBase) {
    const int tid  = threadIdx.x;
    const int warp = tid >> 5, lane = tid & 31;
    const int wm = warp & 1, wn = warp >> 1;   // 2 x 4 warp grid
    const int row0 = rowBase + blockIdx.x * BM;
    const int kbase = blockIdx.y * BN;
    const uint32_t sb = smem_u32(dyn_smem);
    float* s_cbn = (float*)(dyn_smem + SMEM_CBN);

    if (tid < BN) s_cbn[tid] = g_cbnorm[kbase + tid];

    copy_chunk(sb, 0, row0, kbase, tid);
    CP_COMMIT();

    uint32_t c[2][4][2];                       // packed half2 accumulators
#pragma unroll
    for (int i = 0; i < 2; i++)
#pragma unroll
        for (int j = 0; j < 4; j++) { c[i][j][0] = 0u; c[i][j][1] = 0u; }

    for (int ch = 0; ch < NCHUNK; ch++) {
        if (ch + 1 < NCHUNK) {
            copy_chunk(sb + ((ch + 1) & 1) * STAGE_BYTES, ch + 1, row0, kbase, tid);
            CP_COMMIT();
            CP_WAIT(1);
        } else {
            CP_WAIT(0);
        }
        __syncthreads();

        const uint32_t st = sb + (ch & 1) * STAGE_BYTES;
#pragma unroll
        for (int ks = 0; ks < KC / 16; ks++) {
            uint32_t a[2][4];
#pragma unroll
            for (int i = 0; i < 2; i++) {
                uint32_t addr = st + A_OFF +
                    SWZ((uint32_t)((wm * 32 + i * 16 + (lane & 15)) * 128 +
                                   ks * 32 + (lane >> 4) * 16));
                LDSM4(a[i][0], a[i][1], a[i][2], a[i][3], addr);
            }
#pragma unroll
            for (int j = 0; j < 2; j++) {
                uint32_t b0, b1, b2, b3;
                uint32_t addr = st + B_OFF +
                    SWZ((uint32_t)((wn * 32 + j * 16 + (lane & 15)) * 128 +
                                   ks * 32 + (lane >> 4) * 16));
                LDSM4(b0, b1, b2, b3, addr);
#pragma unroll
                for (int i = 0; i < 2; i++) {
                    MMA_F16(c[i][2 * j + 0], a[i], b0, b2);
                    MMA_F16(c[i][2 * j + 1], a[i], b1, b3);
                }
            }
        }
        __syncthreads();
    }

    // ---- Epilogue: score = cbnorm - 2*dot; per-row top-3 ----
    float tv[4][3];
    int   ti[4][3];
#pragma unroll
    for (int r = 0; r < 4; r++)
#pragma unroll
        for (int k = 0; k < 3; k++) { tv[r][k] = 3.4e38f; ti[r][k] = 0; }

#pragma unroll
    for (int i = 0; i < 2; i++)
#pragma unroll
        for (int jj = 0; jj < 4; jj++) {
            int colb = wn * 32 + jj * 8 + (lane & 3) * 2;
            float2 v01 = __half22float2(*(__half2*)&c[i][jj][0]);
            float2 v23 = __half22float2(*(__half2*)&c[i][jj][1]);
            ins3(tv[i * 2 + 0], ti[i * 2 + 0],
                 fmaf(-2.f, v01.x, s_cbn[colb + 0]), kbase + colb + 0);
            ins3(tv[i * 2 + 0], ti[i * 2 + 0],
                 fmaf(-2.f, v01.y, s_cbn[colb + 1]), kbase + colb + 1);
            ins3(tv[i * 2 + 1], ti[i * 2 + 1],
                 fmaf(-2.f, v23.x, s_cbn[colb + 0]), kbase + colb + 0);
            ins3(tv[i * 2 + 1], ti[i * 2 + 1],
                 fmaf(-2.f, v23.y, s_cbn[colb + 1]), kbase + colb + 1);
        }

    // merge across the 4 lanes sharing each row (lanes differ in lane&3)
#pragma unroll
    for (int off = 1; off <= 2; off <<= 1) {
#pragma unroll
        for (int r = 0; r < 4; r++) {
            float pv[3]; int pi[3];
#pragma unroll
            for (int k = 0; k < 3; k++) {
                pv[k] = __shfl_xor_sync(0xffffffffu, tv[r][k], off);
                pi[k] = __shfl_xor_sync(0xffffffffu, ti[r][k], off);
            }
#pragma unroll
            for (int k = 0; k < 3; k++) ins3(tv[r], ti[r], pv[k], pi[k]);
        }
    }

    // stage per-(row, wn) lists into smem (reuse stage region)
    float* smv = (float*)dyn_smem;               // [64][4][3]
    int*   smi = (int*)(dyn_smem + 64 * 4 * 3 * 4);
    if ((lane & 3) == 0) {
        int g = lane >> 2;
#pragma unroll
        for (int i = 0; i < 2; i++)
#pragma unroll
            for (int sub = 0; sub < 2; sub++) {
                int ri = i * 2 + sub;
                int r = wm * 32 + i * 16 + g + sub * 8;
#pragma unroll
                for (int k = 0; k < 3; k++) {
                    smv[(r * 4 + wn) * 3 + k] = tv[ri][k];
                    smi[(r * 4 + wn) * 3 + k] = ti[ri][k];
                }
            }
    }
    __syncthreads();

    if (tid < BM) {
        float fv[3] = {3.4e38f, 3.4e38f, 3.4e38f};
        int   fi[3] = {0, 0, 0};
#pragma unroll
        for (int w = 0; w < 4; w++)
#pragma unroll
            for (int k = 0; k < 3; k++)
                ins3(fv, fi, smv[(tid * 4 + w) * 3 + k], smi[(tid * 4 + w) * 3 + k]);
        size_t base = ((size_t)blockIdx.y * NROWS + row0 + tid) * 3;
#pragma unroll
        for (int k = 0; k < 3; k++) {
            g_tval[base + k] = fv[k];
            g_tidx[base + k] = fi[k];
        }
    }
}

// ---------------------------------------------------------------------------
// Refine: ballot-parallel candidate selection (96 candidates, 3 lane-batches),
// exact fp32 re-scoring; gather zq, indices, loss, counts. The global ticket
// spans BOTH refine launches (2048 blocks total); the last block finalizes.
// ---------------------------------------------------------------------------
__global__ void refine_kernel(const float* __restrict__ ze,
                              const float* __restrict__ cb,
                              float* __restrict__ out,
                              int rowBase) {
    const int warp = threadIdx.x >> 5, lane = threadIdx.x & 31;
    const int row = rowBase + blockIdx.x * 8 + warp;
    __shared__ float s_loss[8];

    const float4* zef = (const float4*)ze;
    const float4* cbf = (const float4*)cb;
    float4 z0 = zef[(size_t)row * 64 + lane * 2 + 0];
    float4 z1 = zef[(size_t)row * 64 + lane * 2 + 1];

    // 96 candidates = 3 full lane-batches
    float av[3]; int id[3];
#pragma unroll
    for (int b = 0; b < 3; b++) {
        int j = b * 32 + lane;
        int s = j / 3, k = j - s * 3;
        size_t a = ((size_t)s * NROWS + row) * 3 + k;
        av[b] = g_tval[a]; id[b] = g_tidx[a];
    }
    float vmin = fminf(av[0], fminf(av[1], av[2]));
#pragma unroll
    for (int o = 16; o; o >>= 1)
        vmin = fminf(vmin, __shfl_xor_sync(0xffffffffu, vmin, o));
    const float thr = vmin + MARGIN;

    uint32_t msk[3];
#pragma unroll
    for (int b = 0; b < 3; b++)
        msk[b] = __ballot_sync(0xffffffffu, av[b] <= thr);

    float bestv = 3.4e38f;
    int   besti = 0x7fffffff;
#pragma unroll 1
    for (int b = 0; b < 3; b++) {
        uint32_t m = msk[b];
        while (m) {
            int src = __ffs(m) - 1;
            m &= m - 1;
            int idx = __shfl_sync(0xffffffffu, id[b], src);
            float4 e0 = cbf[(size_t)idx * 64 + lane * 2 + 0];
            float4 e1 = cbf[(size_t)idx * 64 + lane * 2 + 1];
            float dot = 0.f;
            dot = fmaf(z0.x, e0.x, dot);
            dot = fmaf(z0.y, e0.y, dot);
            dot = fmaf(z0.z, e0.z, dot);
            dot = fmaf(z0.w, e0.w, dot);
            dot = fmaf(z1.x, e1.x, dot);
            dot = fmaf(z1.y, e1.y, dot);
            dot = fmaf(z1.z, e1.z, dot);
            dot = fmaf(z1.w, e1.w, dot);
#pragma unroll
            for (int o = 16; o; o >>= 1)
                dot += __shfl_xor_sync(0xffffffffu, dot, o);
            float sc = fmaf(-2.f, dot, g_cbnorm[idx]);
            if (sc < bestv || (sc == bestv && idx < besti)) {
                bestv = sc; besti = idx;
            }
        }
    }

    if (lane == 0) {
        out[row] = (float)besti;
        atomicAdd(&g_counts[besti], 1);
    }

    // gather zq, write (vectorized), accumulate loss (block-level reduction)
    {
        float4 e0 = cbf[(size_t)besti * 64 + lane * 2 + 0];
        float4 e1 = cbf[(size_t)besti * 64 + lane * 2 + 1];
        float4* qr = (float4*)(out + NROWS + (size_t)row * D);
        qr[lane * 2 + 0] = e0;
        qr[lane * 2 + 1] = e1;
        float sl = 0.f;
        float d0 = e0.x - z0.x; sl = fmaf(d0, d0, sl);
        float d1 = e0.y - z0.y; sl = fmaf(d1, d1, sl);
        float d2 = e0.z - z0.z; sl = fmaf(d2, d2, sl);
        float d3 = e0.w - z0.w; sl = fmaf(d3, d3, sl);
        float d4 = e1.x - z1.x; sl = fmaf(d4, d4, sl);
        float d5 = e1.y - z1.y; sl = fmaf(d5, d5, sl);
        float d6 = e1.z - z1.z; sl = fmaf(d6, d6, sl);
        float d7 = e1.w - z1.w; sl = fmaf(d7, d7, sl);
#pragma unroll
        for (int o = 16; o; o >>= 1) sl += __shfl_xor_sync(0xffffffffu, sl, o);
        if (lane == 0) s_loss[warp] = sl;
    }
    __syncthreads();
    if (threadIdx.x == 0) {
        float sl = 0.f;
#pragma unroll
        for (int w = 0; w < 8; w++) sl += s_loss[w];
        atomicAdd(&g_loss, sl);
    }

    // ---- global finalize ticket (spans both refine launches) ----
    __threadfence();
    __syncthreads();
    __shared__ unsigned int s_ticket;
    if (threadIdx.x == 0) s_ticket = atomicAdd(&g_done, 1u);
    __syncthreads();
    if (s_ticket == (NROWS / 8) - 1) {
        __shared__ float red[256];
        float h = 0.f;
        for (int k = threadIdx.x; k < KCODES; k += 256) {
            float p = (float)g_counts[k] / 10.0f;
            h += p * logf(p + 1e-10f);
        }
        red[threadIdx.x] = h;
        __syncthreads();
        for (int o = 128; o; o >>= 1) {
            if (threadIdx.x < o) red[threadIdx.x] += red[threadIdx.x + o];
            __syncthreads();
        }
        if (threadIdx.x == 0) {
            float loss = g_loss / (float)((size_t)NROWS * D);
            const size_t base = (size_t)NROWS + (size_t)NROWS * D;
            out[base + 0] = loss;
            out[base + 1] = loss;
            out[base + 2] = expf(-red[0]);
        }
    }
}

// ---------------------------------------------------------------------------
extern "C" void kernel_launch(void* const* d_in, const int* in_sizes, int n_in,
                              void* d_out, int out_size) {
    const float* ze = (const float*)d_in[0];
    const float* cb = (const float*)d_in[1];
    float* out = (float*)d_out;

    // Stream/event fork for overlapping refine_a with pass1_b. Created once,
    // on the first (uncaptured) correctness call; reused during capture.
    static cudaStream_t s2 = nullptr;
    static cudaEvent_t evA = nullptr, evRA = nullptr;
    if (s2 == nullptr) {
        cudaStreamCreateWithFlags(&s2, cudaStreamNonBlocking);
        cudaEventCreateWithFlags(&evA, cudaEventDisableTiming);
        cudaEventCreateWithFlags(&evRA, cudaEventDisableTiming);
        cudaFuncSetAttribute(pass1_kernel,
                             cudaFuncAttributeMaxDynamicSharedMemorySize,
                             SMEM_TOTAL);
    }

    prep_kernel<<<ZE_BLOCKS + CB_BLOCKS, 256>>>(ze, cb);

    dim3 grid(HALF_ROWS / BM, KSPLIT);
    // pass1 on rows [0, 8192)
    pass1_kernel<<<grid, 256, SMEM_TOTAL>>>(0);
    cudaEventRecord(evA, 0);
    // pass1 on rows [8192, 16384) — runs next on the main stream
    pass1_kernel<<<grid, 256, SMEM_TOTAL>>>(HALF_ROWS);

    // refine_a on forked stream: overlaps pass1 of the second half
    cudaStreamWaitEvent(s2, evA, 0);
    refine_kernel<<<HALF_ROWS / 8, 256, 0, s2>>>(ze, cb, out, 0);
    cudaEventRecord(evRA, s2);

    // refine_b on the main stream after pass1_b
    refine_kernel<<<HALF_ROWS / 8, 256>>>(ze, cb, out, HALF_ROWS);

    // join the fork so the captured graph's leaf covers refine_a
    cudaStreamWaitEvent(0, evRA, 0);
}

// round 16
// speedup vs baseline: 1.0321x; 1.0321x over previous
#include <cuda_runtime.h>
#include <cuda_fp16.h>
#include <math.h>
#include <stdint.h>

// Problem shape (fixed)
#define D       256
#define NROWS   16384
#define KCODES  4096

// Pass-1 GEMM tiling: CTA 64x128, 8 warps (2m x 4n), warp tile 32x32
#define BM      64
#define BN      128
#define KC      64                 // fp16 elems per staged chunk (=128B rows)
#define NCHUNK  (D / KC)           // 4
#define KSPLIT  (KCODES / BN)      // 32
#define MARGIN  1.5f
#define HALF_ROWS (NROWS / 2)      // 8192

// smem: stage = A(64x128B=8K) + B(128x128B=16K) = 24K, double buffered
#define STAGE_BYTES   24576
#define A_OFF         0
#define B_OFF         8192
#define SMEM_CBN      (2 * STAGE_BYTES)
#define SMEM_TOTAL    (SMEM_CBN + 512)

#define SWZ(x) ((x) ^ (((x) >> 3) & 0x70))

// ---------------------------------------------------------------------------
__device__ __forceinline__ uint32_t smem_u32(const void* p) {
    uint32_t a;
    asm("{ .reg .u64 t; cvta.to.shared.u64 t, %1; cvt.u32.u64 %0, t; }" : "=r"(a) : "l"(p));
    return a;
}
#define CP_ASYNC16(dst, src) \
    asm volatile("cp.async.cg.shared.global [%0], [%1], 16;" :: "r"(dst), "l"(src))
#define CP_COMMIT() asm volatile("cp.async.commit_group;" ::: "memory")
#define CP_WAIT(n)  asm volatile("cp.async.wait_group %0;" :: "n"(n) : "memory")
#define LDSM4(r0, r1, r2, r3, addr) \
    asm volatile("ldmatrix.sync.aligned.m8n8.x4.shared.b16 {%0,%1,%2,%3}, [%4];" \
                 : "=r"(r0), "=r"(r1), "=r"(r2), "=r"(r3) : "r"(addr))
#define MMA_F16(c, a, b0, b1) \
    asm volatile("mma.sync.aligned.m16n8k16.row.col.f16.f16.f16.f16 " \
                 "{%0,%1}, {%2,%3,%4,%5}, {%6,%7}, {%0,%1};" \
                 : "+r"((c)[0]), "+r"((c)[1]) \
                 : "r"((a)[0]), "r"((a)[1]), "r"((a)[2]), "r"((a)[3]), "r"(b0), "r"(b1))

// ---------------------------------------------------------------------------
// Scratch
// ---------------------------------------------------------------------------
__device__ __half g_zeH[NROWS * D];
__device__ __half g_cbH[KCODES * D];
__device__ float g_cbnorm[KCODES];
__device__ int   g_counts[KCODES];
__device__ float g_loss;
__device__ unsigned int g_done;
__device__ float g_tval[KSPLIT * NROWS * 3];   // [split][row][3]
__device__ int   g_tidx[KSPLIT * NROWS * 3];

// ---------------------------------------------------------------------------
// Fused prep: blocks [0,4096) convert ze -> fp16; blocks [4096,4608) convert
// cb -> fp16 + fp32 norms + zero counters.
// ---------------------------------------------------------------------------
#define ZE_BLOCKS ((NROWS * D / 4) / 256)        // 4096
#define CB_BLOCKS (KCODES / 8)                   // 512

__global__ void prep_kernel(const float* __restrict__ ze,
                            const float* __restrict__ cb) {
    const int tid = threadIdx.x;
    if (blockIdx.x < ZE_BLOCKS) {
        int idx = blockIdx.x * 256 + tid;        // float4 index
        float4 v = ((const float4*)ze)[idx];
        __half2* o = (__half2*)g_zeH;
        o[idx * 2 + 0] = __floats2half2_rn(v.x, v.y);
        o[idx * 2 + 1] = __floats2half2_rn(v.z, v.w);
        return;
    }
    const int bb = blockIdx.x - ZE_BLOCKS;
    const int gid = bb * 256 + tid;
    if (gid < KCODES) g_counts[gid] = 0;
    if (gid == 0) { g_loss = 0.f; g_done = 0u; }

    const int warp = tid >> 5, lane = tid & 31;
    const int code = bb * 8 + warp;
    const float* row = cb + (size_t)code * D;
    float s = 0.f;
#pragma unroll
    for (int i = 0; i < D / 32; i++) {
        int j = lane + i * 32;
        float x = row[j];
        g_cbH[(size_t)code * D + j] = __float2half_rn(x);
        s = fmaf(x, x, s);
    }
#pragma unroll
    for (int o = 16; o; o >>= 1) s += __shfl_xor_sync(0xffffffffu, s, o);
    if (lane == 0) g_cbnorm[code] = s;
}

// ---------------------------------------------------------------------------
// top-3 insert (ascending)
// ---------------------------------------------------------------------------
__device__ __forceinline__ void ins3(float* tv, int* ti, float v, int id) {
    if (v < tv[0]) {
        tv[2] = tv[1]; ti[2] = ti[1];
        tv[1] = tv[0]; ti[1] = ti[0];
        tv[0] = v;     ti[0] = id;
    } else if (v < tv[1]) {
        tv[2] = tv[1]; ti[2] = ti[1];
        tv[1] = v;     ti[1] = id;
    } else if (v < tv[2]) {
        tv[2] = v;     ti[2] = id;
    }
}

// ---------------------------------------------------------------------------
// Pass 1: fp16 mma.sync (f16 accum) distance GEMM, fused top-3 per 128-code
// split. grid = (rows/BM, KSPLIT), 256 threads, 4 CTAs/SM.
// ---------------------------------------------------------------------------
extern __shared__ char dyn_smem[];

__device__ __forceinline__ void copy_chunk(uint32_t st, int ch, int row0,
                                           int kbase, int tid) {
    const __half* Az = g_zeH + (size_t)row0 * D + ch * KC;
    const __half* Bz = g_cbH + (size_t)kbase * D + ch * KC;
#pragma unroll
    for (int it = 0; it < 2; it++) {           // A: 64 rows x 8 granules
        int idx = tid + it * 256;
        int r = idx >> 3, g = idx & 7;
        CP_ASYNC16(st + A_OFF + SWZ((uint32_t)(r * 128 + g * 16)),
                   Az + (size_t)r * D + g * 8);
    }
#pragma unroll
    for (int it = 0; it < 4; it++) {           // B: 128 rows x 8 granules
        int idx = tid + it * 256;
        int r = idx >> 3, g = idx & 7;
        CP_ASYNC16(st + B_OFF + SWZ((uint32_t)(r * 128 + g * 16)),
                   Bz + (size_t)r * D + g * 8);
    }
}

__global__ void __launch_bounds__(256, 4) pass1_kernel(int rowBase) {
    const int tid  = threadIdx.x;
    const int warp = tid >> 5, lane = tid & 31;
    const int wm = warp & 1, wn = warp >> 1;   // 2 x 4 warp grid
    const int row0 = rowBase + blockIdx.x * BM;
    const int kbase = blockIdx.y * BN;
    const uint32_t sb = smem_u32(dyn_smem);
    float* s_cbn = (float*)(dyn_smem + SMEM_CBN);

    if (tid < BN) s_cbn[tid] = g_cbnorm[kbase + tid];

    copy_chunk(sb, 0, row0, kbase, tid);
    CP_COMMIT();

    uint32_t c[2][4][2];                       // packed half2 accumulators
#pragma unroll
    for (int i = 0; i < 2; i++)
#pragma unroll
        for (int j = 0; j < 4; j++) { c[i][j][0] = 0u; c[i][j][1] = 0u; }

    for (int ch = 0; ch < NCHUNK; ch++) {
        if (ch + 1 < NCHUNK) {
            copy_chunk(sb + ((ch + 1) & 1) * STAGE_BYTES, ch + 1, row0, kbase, tid);
            CP_COMMIT();
            CP_WAIT(1);
        } else {
            CP_WAIT(0);
        }
        __syncthreads();

        const uint32_t st = sb + (ch & 1) * STAGE_BYTES;
#pragma unroll
        for (int ks = 0; ks < KC / 16; ks++) {
            uint32_t a[2][4];
#pragma unroll
            for (int i = 0; i < 2; i++) {
                uint32_t addr = st + A_OFF +
                    SWZ((uint32_t)((wm * 32 + i * 16 + (lane & 15)) * 128 +
                                   ks * 32 + (lane >> 4) * 16));
                LDSM4(a[i][0], a[i][1], a[i][2], a[i][3], addr);
            }
#pragma unroll
            for (int j = 0; j < 2; j++) {
                uint32_t b0, b1, b2, b3;
                uint32_t addr = st + B_OFF +
                    SWZ((uint32_t)((wn * 32 + j * 16 + (lane & 15)) * 128 +
                                   ks * 32 + (lane >> 4) * 16));
                LDSM4(b0, b1, b2, b3, addr);
#pragma unroll
                for (int i = 0; i < 2; i++) {
                    MMA_F16(c[i][2 * j + 0], a[i], b0, b2);
                    MMA_F16(c[i][2 * j + 1], a[i], b1, b3);
                }
            }
        }
        __syncthreads();
    }

    // ---- Epilogue: score = cbnorm - 2*dot; per-row top-3 ----
    float tv[4][3];
    int   ti[4][3];
#pragma unroll
    for (int r = 0; r < 4; r++)
#pragma unroll
        for (int k = 0; k < 3; k++) { tv[r][k] = 3.4e38f; ti[r][k] = 0; }

#pragma unroll
    for (int i = 0; i < 2; i++)
#pragma unroll
        for (int jj = 0; jj < 4; jj++) {
            int colb = wn * 32 + jj * 8 + (lane & 3) * 2;
            float2 v01 = __half22float2(*(__half2*)&c[i][jj][0]);
            float2 v23 = __half22float2(*(__half2*)&c[i][jj][1]);
            ins3(tv[i * 2 + 0], ti[i * 2 + 0],
                 fmaf(-2.f, v01.x, s_cbn[colb + 0]), kbase + colb + 0);
            ins3(tv[i * 2 + 0], ti[i * 2 + 0],
                 fmaf(-2.f, v01.y, s_cbn[colb + 1]), kbase + colb + 1);
            ins3(tv[i * 2 + 1], ti[i * 2 + 1],
                 fmaf(-2.f, v23.x, s_cbn[colb + 0]), kbase + colb + 0);
            ins3(tv[i * 2 + 1], ti[i * 2 + 1],
                 fmaf(-2.f, v23.y, s_cbn[colb + 1]), kbase + colb + 1);
        }

    // merge across the 4 lanes sharing each row (lanes differ in lane&3)
#pragma unroll
    for (int off = 1; off <= 2; off <<= 1) {
#pragma unroll
        for (int r = 0; r < 4; r++) {
            float pv[3]; int pi[3];
#pragma unroll
            for (int k = 0; k < 3; k++) {
                pv[k] = __shfl_xor_sync(0xffffffffu, tv[r][k], off);
                pi[k] = __shfl_xor_sync(0xffffffffu, ti[r][k], off);
            }
#pragma unroll
            for (int k = 0; k < 3; k++) ins3(tv[r], ti[r], pv[k], pi[k]);
        }
    }

    // stage per-(row, wn) lists into smem (reuse stage region)
    float* smv = (float*)dyn_smem;               // [64][4][3]
    int*   smi = (int*)(dyn_smem + 64 * 4 * 3 * 4);
    if ((lane & 3) == 0) {
        int g = lane >> 2;
#pragma unroll
        for (int i = 0; i < 2; i++)
#pragma unroll
            for (int sub = 0; sub < 2; sub++) {
                int ri = i * 2 + sub;
                int r = wm * 32 + i * 16 + g + sub * 8;
#pragma unroll
                for (int k = 0; k < 3; k++) {
                    smv[(r * 4 + wn) * 3 + k] = tv[ri][k];
                    smi[(r * 4 + wn) * 3 + k] = ti[ri][k];
                }
            }
    }
    __syncthreads();

    if (tid < BM) {
        float fv[3] = {3.4e38f, 3.4e38f, 3.4e38f};
        int   fi[3] = {0, 0, 0};
#pragma unroll
        for (int w = 0; w < 4; w++)
#pragma unroll
            for (int k = 0; k < 3; k++)
                ins3(fv, fi, smv[(tid * 4 + w) * 3 + k], smi[(tid * 4 + w) * 3 + k]);
        size_t base = ((size_t)blockIdx.y * NROWS + row0 + tid) * 3;
#pragma unroll
        for (int k = 0; k < 3; k++) {
            g_tval[base + k] = fv[k];
            g_tidx[base + k] = fi[k];
        }
    }
}

// ---------------------------------------------------------------------------
// Refine: ballot-parallel candidate selection (96 candidates, 3 lane-batches),
// exact fp32 re-scoring; gather zq, indices, loss, counts. The global ticket
// spans BOTH refine launches (2048 blocks total); the last block finalizes.
// ---------------------------------------------------------------------------
__global__ void refine_kernel(const float* __restrict__ ze,
                              const float* __restrict__ cb,
                              float* __restrict__ out,
                              int rowBase) {
    const int warp = threadIdx.x >> 5, lane = threadIdx.x & 31;
    const int row = rowBase + blockIdx.x * 8 + warp;
    __shared__ float s_loss[8];

    const float4* zef = (const float4*)ze;
    const float4* cbf = (const float4*)cb;
    float4 z0 = zef[(size_t)row * 64 + lane * 2 + 0];
    float4 z1 = zef[(size_t)row * 64 + lane * 2 + 1];

    // 96 candidates = 3 full lane-batches
    float av[3]; int id[3];
#pragma unroll
    for (int b = 0; b < 3; b++) {
        int j = b * 32 + lane;
        int s = j / 3, k = j - s * 3;
        size_t a = ((size_t)s * NROWS + row) * 3 + k;
        av[b] = g_tval[a]; id[b] = g_tidx[a];
    }
    float vmin = fminf(av[0], fminf(av[1], av[2]));
#pragma unroll
    for (int o = 16; o; o >>= 1)
        vmin = fminf(vmin, __shfl_xor_sync(0xffffffffu, vmin, o));
    const float thr = vmin + MARGIN;

    uint32_t msk[3];
#pragma unroll
    for (int b = 0; b < 3; b++)
        msk[b] = __ballot_sync(0xffffffffu, av[b] <= thr);

    float bestv = 3.4e38f;
    int   besti = 0x7fffffff;
#pragma unroll 1
    for (int b = 0; b < 3; b++) {
        uint32_t m = msk[b];
        while (m) {
            int src = __ffs(m) - 1;
            m &= m - 1;
            int idx = __shfl_sync(0xffffffffu, id[b], src);
            float4 e0 = cbf[(size_t)idx * 64 + lane * 2 + 0];
            float4 e1 = cbf[(size_t)idx * 64 + lane * 2 + 1];
            float dot = 0.f;
            dot = fmaf(z0.x, e0.x, dot);
            dot = fmaf(z0.y, e0.y, dot);
            dot = fmaf(z0.z, e0.z, dot);
            dot = fmaf(z0.w, e0.w, dot);
            dot = fmaf(z1.x, e1.x, dot);
            dot = fmaf(z1.y, e1.y, dot);
            dot = fmaf(z1.z, e1.z, dot);
            dot = fmaf(z1.w, e1.w, dot);
#pragma unroll
            for (int o = 16; o; o >>= 1)
                dot += __shfl_xor_sync(0xffffffffu, dot, o);
            float sc = fmaf(-2.f, dot, g_cbnorm[idx]);
            if (sc < bestv || (sc == bestv && idx < besti)) {
                bestv = sc; besti = idx;
            }
        }
    }

    if (lane == 0) {
        out[row] = (float)besti;
        atomicAdd(&g_counts[besti], 1);
    }

    // gather zq, write (vectorized), accumulate loss (block-level reduction)
    {
        float4 e0 = cbf[(size_t)besti * 64 + lane * 2 + 0];
        float4 e1 = cbf[(size_t)besti * 64 + lane * 2 + 1];
        float4* qr = (float4*)(out + NROWS + (size_t)row * D);
        qr[lane * 2 + 0] = e0;
        qr[lane * 2 + 1] = e1;
        float sl = 0.f;
        float d0 = e0.x - z0.x; sl = fmaf(d0, d0, sl);
        float d1 = e0.y - z0.y; sl = fmaf(d1, d1, sl);
        float d2 = e0.z - z0.z; sl = fmaf(d2, d2, sl);
        float d3 = e0.w - z0.w; sl = fmaf(d3, d3, sl);
        float d4 = e1.x - z1.x; sl = fmaf(d4, d4, sl);
        float d5 = e1.y - z1.y; sl = fmaf(d5, d5, sl);
        float d6 = e1.z - z1.z; sl = fmaf(d6, d6, sl);
        float d7 = e1.w - z1.w; sl = fmaf(d7, d7, sl);
#pragma unroll
        for (int o = 16; o; o >>= 1) sl += __shfl_xor_sync(0xffffffffu, sl, o);
        if (lane == 0) s_loss[warp] = sl;
    }
    __syncthreads();
    if (threadIdx.x == 0) {
        float sl = 0.f;
#pragma unroll
        for (int w = 0; w < 8; w++) sl += s_loss[w];
        atomicAdd(&g_loss, sl);
    }

    // ---- global finalize ticket (spans both refine launches) ----
    __threadfence();
    __syncthreads();
    __shared__ unsigned int s_ticket;
    if (threadIdx.x == 0) s_ticket = atomicAdd(&g_done, 1u);
    __syncthreads();
    if (s_ticket == (NROWS / 8) - 1) {
        __shared__ float red[256];
        float h = 0.f;
        for (int k = threadIdx.x; k < KCODES; k += 256) {
            float p = (float)g_counts[k] / 10.0f;
            h += p * logf(p + 1e-10f);
        }
        red[threadIdx.x] = h;
        __syncthreads();
        for (int o = 128; o; o >>= 1) {
            if (threadIdx.x < o) red[threadIdx.x] += red[threadIdx.x + o];
            __syncthreads();
        }
        if (threadIdx.x == 0) {
            float loss = g_loss / (float)((size_t)NROWS * D);
            const size_t base = (size_t)NROWS + (size_t)NROWS * D;
            out[base + 0] = loss;
            out[base + 1] = loss;
            out[base + 2] = expf(-red[0]);
        }
    }
}

// ---------------------------------------------------------------------------
extern "C" void kernel_launch(void* const* d_in, const int* in_sizes, int n_in,
                              void* d_out, int out_size) {
    const float* ze = (const float*)d_in[0];
    const float* cb = (const float*)d_in[1];
    float* out = (float*)d_out;

    // Two INDEPENDENT pass1->refine chains on parallel streams. Created once
    // on the first (uncaptured) correctness call; reused during capture.
    static cudaStream_t s2 = nullptr;
    static cudaEvent_t evPrep = nullptr, evB = nullptr;
    if (s2 == nullptr) {
        cudaStreamCreateWithFlags(&s2, cudaStreamNonBlocking);
        cudaEventCreateWithFlags(&evPrep, cudaEventDisableTiming);
        cudaEventCreateWithFlags(&evB, cudaEventDisableTiming);
        cudaFuncSetAttribute(pass1_kernel,
                             cudaFuncAttributeMaxDynamicSharedMemorySize,
                             SMEM_TOTAL);
    }

    prep_kernel<<<ZE_BLOCKS + CB_BLOCKS, 256>>>(ze, cb);
    cudaEventRecord(evPrep, 0);
    cudaStreamWaitEvent(s2, evPrep, 0);

    dim3 grid(HALF_ROWS / BM, KSPLIT);
    // chain A on stream 0: rows [0, 8192)
    pass1_kernel<<<grid, 256, SMEM_TOTAL>>>(0);
    // chain B on stream s2: rows [8192, 16384) — runs CONCURRENTLY
    pass1_kernel<<<grid, 256, SMEM_TOTAL, s2>>>(HALF_ROWS);

    refine_kernel<<<HALF_ROWS / 8, 256>>>(ze, cb, out, 0);
    refine_kernel<<<HALF_ROWS / 8, 256, 0, s2>>>(ze, cb, out, HALF_ROWS);

    // join chain B back into stream 0
    cudaEventRecord(evB, s2);
    cudaStreamWaitEvent(0, evB, 0);
}